// round 17
// baseline (speedup 1.0000x reference)
#include <cuda_runtime.h>
#include <cuda_fp16.h>
#include <cstdint>
#include <math.h>

#define BH 16
#define LSEQ 2048
#define DH 64
#define OUT_ELE (LSEQ * DH * BH)
#define ATT_ELE ((size_t)BH * LSEQ * LSEQ)

__device__ __half g_Kf[BH * LSEQ * DH];
__device__ __half g_Vtf[BH * DH * LSEQ];

__device__ __forceinline__ uint32_t smem_u32(const void* p) {
    uint32_t a;
    asm("{ .reg .u64 t; cvta.to.shared.u64 t, %1; cvt.u32.u64 %0, t; }" : "=r"(a) : "l"(p));
    return a;
}
__device__ __forceinline__ void ldsm4(uint32_t* r, uint32_t addr) {
    asm volatile("ldmatrix.sync.aligned.m8n8.x4.shared.b16 {%0,%1,%2,%3}, [%4];"
                 : "=r"(r[0]), "=r"(r[1]), "=r"(r[2]), "=r"(r[3]) : "r"(addr));
}
__device__ __forceinline__ void mma16816(float* c, const uint32_t* a, uint32_t b0, uint32_t b1) {
    asm("mma.sync.aligned.m16n8k16.row.col.f32.f16.f16.f32 "
        "{%0,%1,%2,%3}, {%4,%5,%6,%7}, {%8,%9}, {%0,%1,%2,%3};"
        : "+f"(c[0]), "+f"(c[1]), "+f"(c[2]), "+f"(c[3])
        : "r"(a[0]), "r"(a[1]), "r"(a[2]), "r"(a[3]), "r"(b0), "r"(b1));
}
__device__ __forceinline__ void split2h(float a, float b, uint32_t& hi, uint32_t& lo) {
    __half ah = __float2half_rn(a), bh = __float2half_rn(b);
    __half al = __float2half_rn(a - __half2float(ah));
    __half bl = __float2half_rn(b - __half2float(bh));
    __half2 H = __halves2half2(ah, bh);
    __half2 L = __halves2half2(al, bl);
    hi = *reinterpret_cast<uint32_t*>(&H);
    lo = *reinterpret_cast<uint32_t*>(&L);
}
__device__ __forceinline__ uint32_t pack2h(float a, float b) {
    __half2 H = __halves2half2(__float2half_rn(a), __float2half_rn(b));
    return *reinterpret_cast<uint32_t*>(&H);
}
__device__ __forceinline__ void cpasync16(uint32_t dst, const void* src) {
    asm volatile("cp.async.cg.shared.global [%0], [%1], 16;" :: "r"(dst), "l"(src));
}
#define CP_COMMIT() asm volatile("cp.async.commit_group;" ::: "memory")
#define CP_WAIT0()  asm volatile("cp.async.wait_group 0;" ::: "memory")

// 2 exps per MUFU via ex2.approx.f16x2 (sweep-1 stats only; outputs use fp32 exp)
__device__ __forceinline__ float exp2sum_h2(float a, float b) {
    __half2 h = __floats2half2_rn(a * 1.44269504f, b * 1.44269504f);
    uint32_t u = *reinterpret_cast<uint32_t*>(&h);
    uint32_t r;
    asm("ex2.approx.f16x2 %0, %1;" : "=r"(r) : "r"(u));
    __half2 e = *reinterpret_cast<__half2*>(&r);
    float2 f = __half22float2(e);
    return f.x + f.y;
}

// ---------------- Prepass: K (2048 blocks) + V (256 blocks), one launch ----------------
__global__ void prep_kv(const float* __restrict__ k, const float* __restrict__ v) {
    __shared__ float vs[128 * 65];
    const int blk = blockIdx.x, tid = threadIdx.x;
    if (blk < 2048) {
        int idx = blk * 256 + tid;
        float4 x = ((const float4*)k)[idx];
        ((uint2*)g_Kf)[idx] = make_uint2(pack2h(x.x, x.y), pack2h(x.z, x.w));
        return;
    }
    const int bb = (blk - 2048) >> 4, st = (blk - 2048) & 15;
    const float4* vp = (const float4*)(v + ((size_t)(bb * LSEQ + st * 128)) * DH);
#pragma unroll
    for (int it = 0; it < 8; ++it) {
        int fi = it * 256 + tid;
        int s = fi >> 4, d4 = fi & 15;
        float4 x = vp[fi];
        vs[s * 65 + d4 * 4 + 0] = x.x;
        vs[s * 65 + d4 * 4 + 1] = x.y;
        vs[s * 65 + d4 * 4 + 2] = x.z;
        vs[s * 65 + d4 * 4 + 3] = x.w;
    }
    __syncthreads();
#pragma unroll
    for (int it = 0; it < 4; ++it) {
        int fo = it * 256 + tid;
        int d = fo >> 4, cu = fo & 15;
        uint32_t hw[4];
#pragma unroll
        for (int j = 0; j < 4; ++j)
            hw[j] = pack2h(vs[(cu * 8 + 2 * j) * 65 + d], vs[(cu * 8 + 2 * j + 1) * 65 + d]);
        size_t o = ((size_t)(bb * DH + d)) * LSEQ + st * 128 + cu * 8;
        *(uint4*)(g_Vtf + o) = make_uint4(hw[0], hw[1], hw[2], hw[3]);
    }
}

// ---------------- Fused attention (128 threads, 4 warps, 64 q-rows/CTA) ----------------
// Q hi 0..8K, Q lo 8K..16K (split in-kernel from fp32 Q)
// sweep1: K256 bufs at 16K..48K, 48K..80K (32K each)
// sweep2: K bufs 16K..32K, 32K..48K | V bufs 48K..64K, 64K..80K (16K each)
// lzs 80K (512B). Total 82432 -> 2 CTAs/SM.
#define SQH 0
#define SQL 8192
#define SK1(i) (16384 + (i) * 32768)
#define SK(i) (16384 + (i) * 16384)
#define SV(i) (49152 + (i) * 16384)
#define SLZ 81920
#define SMEM_TOT 82432

__global__ void __launch_bounds__(128, 2)
sdpa_fused(const float* __restrict__ q, float* __restrict__ attn,
           float* __restrict__ lattn, float* __restrict__ outp) {
    extern __shared__ char sm[];
    const uint32_t sb = smem_u32(sm);
    const int tid = threadIdx.x, lane = tid & 31, w = tid >> 5;   // w in 0..3
    const int b = blockIdx.y, qbase = blockIdx.x * 64;

    const int arow = lane & 15, achk = lane >> 4;
    const int brow = ((lane >> 4) << 3) + (lane & 7), bch = (lane >> 3) & 1;
    const int rq = lane >> 2, qd = lane & 3;

    const char* kf_base = (const char*)(g_Kf + (size_t)b * LSEQ * DH);
    const char* vf_base = (const char*)(g_Vtf + (size_t)b * DH * LSEQ);

    // sweep1 K chunk (256 seq x 64 d = 32KB)
#define LOAD_K256(buf, u) do {                                                 \
        const char* _s = kf_base + (size_t)(u) * 32768;                        \
        _Pragma("unroll")                                                      \
        for (int r = 0; r < 16; ++r) {                                         \
            int fo = r * 128 + tid;                                            \
            int row = fo >> 3, cu = fo & 7;                                    \
            uint32_t off = (uint32_t)row * 128 + ((cu ^ (row & 7)) << 4);      \
            cpasync16(sb + (buf) + off, _s + fo * 16);                         \
        }                                                                      \
    } while (0)

    // sweep2 K chunk (128 seq x 64 d = 16KB)
#define LOAD_K(buf, u) do {                                                    \
        const char* _s = kf_base + (size_t)(u) * 16384;                        \
        _Pragma("unroll")                                                      \
        for (int r = 0; r < 8; ++r) {                                          \
            int fo = r * 128 + tid;                                            \
            int row = fo >> 3, cu = fo & 7;                                    \
            uint32_t off = (uint32_t)row * 128 + ((cu ^ (row & 7)) << 4);      \
            cpasync16(sb + (buf) + off, _s + fo * 16);                         \
        }                                                                      \
    } while (0)

    // V chunk (64 d x 128 seq = 16KB, 256B rows)
#define LOAD_V(buf, u) do {                                                    \
        _Pragma("unroll")                                                      \
        for (int r = 0; r < 8; ++r) {                                          \
            int fo = r * 128 + tid;                                            \
            int row = fo >> 4, cu = fo & 15;                                   \
            uint32_t off = (uint32_t)row * 256 + ((cu ^ (row & 15)) << 4);     \
            size_t sof = (size_t)row * (LSEQ * 2) + (size_t)(u) * 256 + cu * 16; \
            cpasync16(sb + (buf) + off, vf_base + sof);                        \
        }                                                                      \
    } while (0)

    // ---- prologue: K256 chunk 0 (async) + in-register Q load/split/STS ----
    LOAD_K256(SK1(0), 0);
    CP_COMMIT();
    {
        const float4* qp = (const float4*)(q + (size_t)(b * LSEQ + qbase) * DH);
#pragma unroll
        for (int r = 0; r < 8; ++r) {
            int fi = r * 128 + tid;           // 1024 float4s = 64 rows x 16
            int row = fi >> 4, d4 = fi & 15;
            float4 x = qp[fi];
            x.x *= 0.125f; x.y *= 0.125f; x.z *= 0.125f; x.w *= 0.125f;
            uint32_t h0, l0, h1, l1;
            split2h(x.x, x.y, h0, l0);
            split2h(x.z, x.w, h1, l1);
            uint32_t off = (uint32_t)row * 128 +
                           ((((d4 >> 1) ^ (row & 7)) << 4) | ((d4 & 1) << 3));
            *(uint2*)(sm + SQH + off) = make_uint2(h0, h1);
            *(uint2*)(sm + SQL + off) = make_uint2(l0, l1);
        }
    }

    uint32_t aQh[4][4], aQl[4][4];
    float lrun[2] = {0.f, 0.f};

    // 1-term QK over a 128-seq sub-tile at byte base kb
#define COMPUTE_QK1(c, kb) do {                                                \
        _Pragma("unroll")                                                      \
        for (int nt = 0; nt < 16; ++nt) {                                      \
            c[nt][0] = 0.f; c[nt][1] = 0.f; c[nt][2] = 0.f; c[nt][3] = 0.f;    \
        }                                                                      \
        _Pragma("unroll")                                                      \
        for (int ks = 0; ks < 4; ++ks) {                                       \
            _Pragma("unroll")                                                  \
            for (int pp = 0; pp < 4; ++pp) {                                   \
                int row0 = (2 * pp) * 16 + brow;                               \
                int row1 = row0 + 16;                                          \
                uint32_t ad0 = sb + (kb) + row0 * 128 +                        \
                               (((ks * 2 + bch) ^ (row0 & 7)) << 4);           \
                uint32_t ad1 = sb + (kb) + row1 * 128 +                        \
                               (((ks * 2 + bch) ^ (row1 & 7)) << 4);           \
                uint32_t b0[4], b1[4];                                         \
                ldsm4(b0, ad0);                                                \
                ldsm4(b1, ad1);                                                \
                mma16816(c[4*pp+0], aQh[ks], b0[0], b0[1]);                    \
                mma16816(c[4*pp+1], aQh[ks], b0[2], b0[3]);                    \
                mma16816(c[4*pp+2], aQh[ks], b1[0], b1[1]);                    \
                mma16816(c[4*pp+3], aQh[ks], b1[2], b1[3]);                    \
            }                                                                  \
        }                                                                      \
    } while (0)

    // 2-term QK (sweep 2)
#define COMPUTE_QK2(c, kb) do {                                                \
        _Pragma("unroll")                                                      \
        for (int nt = 0; nt < 16; ++nt) {                                      \
            c[nt][0] = 0.f; c[nt][1] = 0.f; c[nt][2] = 0.f; c[nt][3] = 0.f;    \
        }                                                                      \
        _Pragma("unroll")                                                      \
        for (int ks = 0; ks < 4; ++ks) {                                       \
            _Pragma("unroll")                                                  \
            for (int pp = 0; pp < 4; ++pp) {                                   \
                int row0 = (2 * pp) * 16 + brow;                               \
                int row1 = row0 + 16;                                          \
                uint32_t ad0 = sb + (kb) + row0 * 128 +                        \
                               (((ks * 2 + bch) ^ (row0 & 7)) << 4);           \
                uint32_t ad1 = sb + (kb) + row1 * 128 +                        \
                               (((ks * 2 + bch) ^ (row1 & 7)) << 4);           \
                uint32_t b0[4], b1[4];                                         \
                ldsm4(b0, ad0);                                                \
                ldsm4(b1, ad1);                                                \
                mma16816(c[4*pp+0], aQh[ks], b0[0], b0[1]);                    \
                mma16816(c[4*pp+1], aQh[ks], b0[2], b0[3]);                    \
                mma16816(c[4*pp+2], aQh[ks], b1[0], b1[1]);                    \
                mma16816(c[4*pp+3], aQh[ks], b1[2], b1[3]);                    \
                mma16816(c[4*pp+0], aQl[ks], b0[0], b0[1]);                    \
                mma16816(c[4*pp+1], aQl[ks], b0[2], b0[3]);                    \
                mma16816(c[4*pp+2], aQl[ks], b1[0], b1[1]);                    \
                mma16816(c[4*pp+3], aQl[ks], b1[2], b1[3]);                    \
            }                                                                  \
        }                                                                      \
    } while (0)

    // ================= Sweep 1: sumexp (f16x2 ex2), 8 chunks of 256 =================
    for (int u = 0; u < 8; ++u) {
        CP_WAIT0();
        __syncthreads();
        if (u < 7) {
            LOAD_K256(SK1((u + 1) & 1), u + 1);
            CP_COMMIT();
        }
        if (u == 0) {
#pragma unroll
            for (int ks = 0; ks < 4; ++ks) {
                int row = w * 16 + arow;
                uint32_t ad = sb + SQH + row * 128 + (((ks * 2 + achk) ^ (row & 7)) << 4);
                ldsm4(aQh[ks], ad);
            }
        }
#pragma unroll
        for (int half = 0; half < 2; ++half) {
            float c[16][4];
            COMPUTE_QK1(c, SK1(u & 1) + half * 16384);
#pragma unroll
            for (int h = 0; h < 2; ++h) {
                float sum = 0.f;
#pragma unroll
                for (int nt = 0; nt < 16; ++nt)
                    sum += exp2sum_h2(c[nt][2 * h], c[nt][2 * h + 1]);
                lrun[h] += sum;
            }
        }
    }

    // ---- logZ = log(sum): quad reduce ----
    float* lzs = (float*)(sm + SLZ);
#pragma unroll
    for (int h = 0; h < 2; ++h) {
        float l = lrun[h];
        l += __shfl_xor_sync(0xffffffffu, l, 1);
        l += __shfl_xor_sync(0xffffffffu, l, 2);
        if (qd == 0) lzs[w * 16 + rq + 8 * h] = logf(l);
    }
    __syncwarp();
    const float lz0 = lzs[w * 16 + rq];
    const float lz1 = lzs[w * 16 + rq + 8];

    // ================= Sweep 2: 2-term QK, emit, 2-term PV, 16 chunks =================
    float o[8][4];
#pragma unroll
    for (int g = 0; g < 8; ++g)
#pragma unroll
        for (int j = 0; j < 4; ++j) o[g][j] = 0.f;

    __syncthreads();
    LOAD_K(SK(0), 0);
    LOAD_V(SV(0), 0);
    CP_COMMIT();

#pragma unroll
    for (int ks = 0; ks < 4; ++ks) {
        int row = w * 16 + arow;
        uint32_t ad = sb + SQL + row * 128 + (((ks * 2 + achk) ^ (row & 7)) << 4);
        ldsm4(aQl[ks], ad);
    }

    float* aRow = attn + ((size_t)(b * LSEQ + qbase + w * 16 + rq)) * LSEQ + qd * 2;
    float* lRow = lattn + ((size_t)(b * LSEQ + qbase + w * 16 + rq)) * LSEQ + qd * 2;

    for (int u = 0; u < 16; ++u) {
        CP_WAIT0();
        __syncthreads();
        if (u < 15) {
            LOAD_K(SK((u + 1) & 1), u + 1);
            LOAD_V(SV((u + 1) & 1), u + 1);
            CP_COMMIT();
        }

        float c[16][4];
        COMPUTE_QK2(c, SK(u & 1));

        uint32_t aPh[8][4], aPl[8][4];
        float* aT = aRow + u * 128;
        float* lT = lRow + u * 128;
#pragma unroll
        for (int kc = 0; kc < 8; ++kc) {
#pragma unroll
            for (int qq = 0; qq < 2; ++qq) {
                const int nt = 2 * kc + qq;
                float la0 = c[nt][0] - lz0, la1 = c[nt][1] - lz0;
                float la2 = c[nt][2] - lz1, la3 = c[nt][3] - lz1;
                float p0 = __expf(la0), p1 = __expf(la1);
                float p2 = __expf(la2), p3 = __expf(la3);
                *(float2*)(aT + nt * 8) = make_float2(p0, p1);
                *(float2*)(aT + 8 * LSEQ + nt * 8) = make_float2(p2, p3);
                *(float2*)(lT + nt * 8) = make_float2(la0, la1);
                *(float2*)(lT + 8 * LSEQ + nt * 8) = make_float2(la2, la3);
                __half h0 = __float2half_rn(p0), h1 = __float2half_rn(p1);
                __half h2 = __float2half_rn(p2), h3 = __float2half_rn(p3);
                __half2 H01 = __halves2half2(h0, h1), H23 = __halves2half2(h2, h3);
                aPh[kc][qq * 2 + 0] = *reinterpret_cast<uint32_t*>(&H01);
                aPh[kc][qq * 2 + 1] = *reinterpret_cast<uint32_t*>(&H23);
                __half2 L01 = __halves2half2(__float2half_rn(p0 - __half2float(h0)),
                                             __float2half_rn(p1 - __half2float(h1)));
                __half2 L23 = __halves2half2(__float2half_rn(p2 - __half2float(h2)),
                                             __float2half_rn(p3 - __half2float(h3)));
                aPl[kc][qq * 2 + 0] = *reinterpret_cast<uint32_t*>(&L01);
                aPl[kc][qq * 2 + 1] = *reinterpret_cast<uint32_t*>(&L23);
            }
        }

        const uint32_t vb = sb + SV(u & 1);
#pragma unroll
        for (int kc = 0; kc < 8; ++kc) {
#pragma unroll
            for (int gg = 0; gg < 2; ++gg) {
                int row0 = gg * 32 + brow;
                int row1 = row0 + 16;
                uint32_t ad0 = vb + row0 * 256 + (((kc * 2 + bch) ^ (row0 & 15)) << 4);
                uint32_t ad1 = vb + row1 * 256 + (((kc * 2 + bch) ^ (row1 & 15)) << 4);
                uint32_t v0[4], v1[4];
                ldsm4(v0, ad0);
                ldsm4(v1, ad1);
                mma16816(o[4*gg+0], aPh[kc], v0[0], v0[1]);
                mma16816(o[4*gg+1], aPh[kc], v0[2], v0[3]);
                mma16816(o[4*gg+2], aPh[kc], v1[0], v1[1]);
                mma16816(o[4*gg+3], aPh[kc], v1[2], v1[3]);
                mma16816(o[4*gg+0], aPl[kc], v0[0], v0[1]);
                mma16816(o[4*gg+1], aPl[kc], v0[2], v0[3]);
                mma16816(o[4*gg+2], aPl[kc], v1[0], v1[1]);
                mma16816(o[4*gg+3], aPl[kc], v1[2], v1[3]);
            }
        }
    }

    // ---- head-folded output ----
    {
        int qr = qbase + w * 16 + rq;
        float* dp = outp + (size_t)qr * (DH * BH) + b * DH + qd * 2;
#pragma unroll
        for (int g = 0; g < 8; ++g) {
            *(float2*)(dp + g * 8) = make_float2(o[g][0], o[g][1]);
            *(float2*)(dp + 8 * (DH * BH) + g * 8) = make_float2(o[g][2], o[g][3]);
        }
    }
}

extern "C" void kernel_launch(void* const* d_in, const int* in_sizes, int n_in,
                              void* d_out, int out_size) {
    const float* q = (const float*)d_in[0];
    const float* k = (const float*)d_in[1];
    const float* v = (const float*)d_in[2];

    float* outp = (float*)d_out;
    float* attn = outp + OUT_ELE;
    float* lattn = attn + ATT_ELE;

    cudaFuncSetAttribute(sdpa_fused, cudaFuncAttributeMaxDynamicSharedMemorySize, SMEM_TOT);

    prep_kv<<<2304, 256>>>(k, v);

    dim3 grid(LSEQ / 64, BH);
    sdpa_fused<<<grid, 128, SMEM_TOT>>>(q, attn, lattn, outp);
}